// round 2
// baseline (speedup 1.0000x reference)
#include <cuda_runtime.h>
#include <math_constants.h>

#define NM 1024
#define HH 256
#define WW 256
#define HW (HH*WW)

// ---------------- device scratch (no allocations allowed) ----------------
__device__ int   g_hi[NM];
__device__ int   g_lo[NM];
__device__ int   g_mnx[NM];
__device__ int   g_mxx[NM];
__device__ int   g_mny[NM];
__device__ int   g_mxy[NM];
__device__ float g_gated[NM];

// ---------------- pass 1: per-mask stats (streaming read) ----------------
// One block per mask, 256 threads, float4 loads. Computes:
//   hi = #(logit > 1), lo = #(logit > -1), bbox of (logit > 0).
__global__ __launch_bounds__(256) void stats_kernel(const float* __restrict__ logits) {
    const int n = blockIdx.x;
    const float4* __restrict__ p = (const float4*)(logits + (size_t)n * HW);

    int hi = 0, lo = 0;
    int mnx = WW, mxx = -1, mny = HH, mxy = -1;

    #pragma unroll 4
    for (int q = threadIdx.x; q < (HW / 4); q += 256) {
        float4 v = p[q];
        int e = q << 2;
        int y = e >> 8;          // WW == 256
        int x = e & (WW - 1);
        hi += (v.x > 1.f) + (v.y > 1.f) + (v.z > 1.f) + (v.w > 1.f);
        lo += (v.x > -1.f) + (v.y > -1.f) + (v.z > -1.f) + (v.w > -1.f);
        bool p0 = v.x > 0.f, p1 = v.y > 0.f, p2 = v.z > 0.f, p3 = v.w > 0.f;
        if (p0 | p1 | p2 | p3) {
            mny = min(mny, y); mxy = max(mxy, y);
            if (p0) { mnx = min(mnx, x);     mxx = max(mxx, x);     }
            if (p1) { mnx = min(mnx, x + 1); mxx = max(mxx, x + 1); }
            if (p2) { mnx = min(mnx, x + 2); mxx = max(mxx, x + 2); }
            if (p3) { mnx = min(mnx, x + 3); mxx = max(mxx, x + 3); }
        }
    }

    // warp reduce
    #pragma unroll
    for (int o = 16; o > 0; o >>= 1) {
        hi  += __shfl_xor_sync(0xffffffffu, hi, o);
        lo  += __shfl_xor_sync(0xffffffffu, lo, o);
        mnx  = min(mnx, __shfl_xor_sync(0xffffffffu, mnx, o));
        mxx  = max(mxx, __shfl_xor_sync(0xffffffffu, mxx, o));
        mny  = min(mny, __shfl_xor_sync(0xffffffffu, mny, o));
        mxy  = max(mxy, __shfl_xor_sync(0xffffffffu, mxy, o));
    }

    __shared__ int s_hi[8], s_lo[8], s_mnx[8], s_mxx[8], s_mny[8], s_mxy[8];
    int w = threadIdx.x >> 5;
    if ((threadIdx.x & 31) == 0) {
        s_hi[w] = hi; s_lo[w] = lo;
        s_mnx[w] = mnx; s_mxx[w] = mxx; s_mny[w] = mny; s_mxy[w] = mxy;
    }
    __syncthreads();
    if (threadIdx.x == 0) {
        int thi = 0, tlo = 0, tmnx = WW, tmxx = -1, tmny = HH, tmxy = -1;
        #pragma unroll
        for (int i = 0; i < 8; i++) {
            thi += s_hi[i]; tlo += s_lo[i];
            tmnx = min(tmnx, s_mnx[i]); tmxx = max(tmxx, s_mxx[i]);
            tmny = min(tmny, s_mny[i]); tmxy = max(tmxy, s_mxy[i]);
        }
        g_hi[n] = thi; g_lo[n] = tlo;
        g_mnx[n] = tmnx; g_mxx[n] = tmxx; g_mny[n] = tmny; g_mxy[n] = tmxy;
    }
}

// ---------------- pass 2: validity + bitonic sort + greedy NMS ----------------
// Single block, 1024 threads (one per mask).
__global__ __launch_bounds__(NM) void nms_kernel(const float* __restrict__ iou_preds,
                                                 float* __restrict__ out_keep,
                                                 float* __restrict__ out_boxes) {
    __shared__ float  skey[NM];
    __shared__ int    sidx[NM];
    __shared__ float4 sboxO[NM];   // boxes by original index
    __shared__ float4 sboxS[NM];   // boxes in sorted order
    __shared__ unsigned char skeep[NM];

    const int t = threadIdx.x;

    float sc = iou_preds[t];
    float stab = (float)g_hi[t] / fmaxf((float)g_lo[t], 1.0f);
    bool valid = (sc > 0.88f) && (stab >= 0.95f);

    int mxy = g_mxy[t];
    bool empty = (mxy < 0);
    float4 box;
    if (empty) box = make_float4(0.f, 0.f, 0.f, 0.f);
    else       box = make_float4((float)g_mnx[t], (float)g_mny[t],
                                 (float)g_mxx[t], (float)mxy);  // [left, top, right, bottom]

    sboxO[t] = box;
    skey[t]  = valid ? sc : -CUDART_INF_F;
    sidx[t]  = t;

    if (out_boxes) {
        out_boxes[4 * t + 0] = box.x;
        out_boxes[4 * t + 1] = box.y;
        out_boxes[4 * t + 2] = box.z;
        out_boxes[4 * t + 3] = box.w;
    }
    __syncthreads();

    // bitonic sort, descending by key (scores distinct; -inf ties don't matter)
    for (int k = 2; k <= NM; k <<= 1) {
        for (int j = k >> 1; j > 0; j >>= 1) {
            int ixj = t ^ j;
            if (ixj > t) {
                float a = skey[t], b = skey[ixj];
                bool descend = ((t & k) == 0);
                if (descend ? (a < b) : (a > b)) {
                    skey[t] = b; skey[ixj] = a;
                    int ti = sidx[t]; sidx[t] = sidx[ixj]; sidx[ixj] = ti;
                }
            }
            __syncthreads();
        }
    }

    const int orig = sidx[t];
    const bool vsorted = (skey[t] > -CUDART_INF_F);
    sboxS[t] = sboxO[orig];
    skeep[t] = vsorted ? 1 : 0;
    int nvalid = __syncthreads_count(vsorted);  // barrier + broadcast count

    float4 bt = sboxS[t];
    float area_t = fmaxf(bt.z - bt.x, 0.f) * fmaxf(bt.w - bt.y, 0.f);

    // greedy suppression: only the first nvalid sorted entries can suppress
    for (int i = 0; i < nvalid; i++) {
        __syncthreads();
        bool ki = skeep[i] != 0;
        float4 bi = sboxS[i];
        if (ki && t > i && skeep[t]) {
            float x0 = fmaxf(bi.x, bt.x), y0 = fmaxf(bi.y, bt.y);
            float x1 = fminf(bi.z, bt.z), y1 = fminf(bi.w, bt.w);
            float inter = fmaxf(x1 - x0, 0.f) * fmaxf(y1 - y0, 0.f);
            float area_i = fmaxf(bi.z - bi.x, 0.f) * fmaxf(bi.w - bi.y, 0.f);
            float iou = inter / fmaxf(area_i + area_t - inter, 1e-6f);
            if (iou > 0.7f) skeep[t] = 0;
        }
    }
    __syncthreads();

    bool kept = skeep[t] != 0;
    g_gated[orig] = kept ? skey[t] : 0.f;
    if (out_keep) out_keep[orig] = kept ? 1.f : 0.f;
}

// ---------------- pass 3: gated sigmoid output ----------------
// 64 blocks per mask x 256 threads x float4. Suppressed masks: pure zero-store,
// no logits read -> saves ~90% of the read traffic in this pass.
__global__ __launch_bounds__(256) void gate_kernel(const float* __restrict__ logits,
                                                   float* __restrict__ out) {
    const int b = blockIdx.x;
    const int n = b >> 6;                       // 64 blocks per mask
    const size_t base = ((size_t)b << 10) + ((size_t)threadIdx.x << 2);
    float g = g_gated[n];
    float4* o = (float4*)(out + base);
    if (g == 0.f) {
        *o = make_float4(0.f, 0.f, 0.f, 0.f);
    } else {
        float4 v = *(const float4*)(logits + base);
        float4 r;
        r.x = g / (1.f + __expf(-v.x));
        r.y = g / (1.f + __expf(-v.y));
        r.z = g / (1.f + __expf(-v.z));
        r.w = g / (1.f + __expf(-v.w));
        *o = r;
    }
}

// ---------------- launch ----------------
extern "C" void kernel_launch(void* const* d_in, const int* in_sizes, int n_in,
                              void* d_out, int out_size) {
    const float* logits;
    const float* iou;
    if (in_sizes[0] == NM) { iou = (const float*)d_in[0]; logits = (const float*)d_in[1]; }
    else                   { logits = (const float*)d_in[0]; iou = (const float*)d_in[1]; }

    float* out = (float*)d_out;
    const size_t nhw = (size_t)NM * HW;
    float* out_keep  = nullptr;
    float* out_boxes = nullptr;
    if ((size_t)out_size >= nhw + NM)          out_keep  = out + nhw;
    if ((size_t)out_size >= nhw + NM + 4 * NM) out_boxes = out + nhw + NM;

    stats_kernel<<<NM, 256>>>(logits);
    nms_kernel<<<1, NM>>>(iou, out_keep, out_boxes);
    gate_kernel<<<NM * (HW / 1024), 256>>>(logits, out);
}